// round 2
// baseline (speedup 1.0000x reference)
#include <cuda_runtime.h>
#include <math.h>

// Problem constants
#define B   2
#define L   768
#define H   12
#define DH  64
#define D   8
#define DS  8
#define E   768
#define BH  (B*H)
#define QT  96          // q-tiles: 8 rows per block -> 96 tiles of L=768
#define NPART (BH*D*QT)

#define RSQRT_DS 0.35355339059327373f   // 1/sqrt(8)
#define EPS_TERM 1.3815510557964274e-5f // -1e-6 * ln(1e-6)

// Scratch (static device arrays; no runtime allocation)
__device__ float g_Q[BH*D*L*DS];     // [b,h,d,l,s]
__device__ float g_K[BH*D*L*DS];     // [b,h,d,l,s]
__device__ float g_V[BH*L*DH];       // [b,h,l,dh]
__device__ float g_part[NPART*3];    // per-block partial sums (S2, rowmax, ent)
__device__ float g_stats[B*D*4];     // var, max, ent, hhi
__device__ float g_w[B*D];           // depth weights

// ---------------------------------------------------------------------------
// Kernel 1: QKV projections. z = 0:Q, 1:K, 2:V.
// C[1536,768] = X[1536,768] @ W[768,768] + b, stored into transposed layouts.
// ---------------------------------------------------------------------------
__global__ __launch_bounds__(256)
void qkv_gemm(const float* __restrict__ X,
              const float* __restrict__ Wq, const float* __restrict__ bq,
              const float* __restrict__ Wk, const float* __restrict__ bk,
              const float* __restrict__ Wv, const float* __restrict__ bv)
{
    int z = blockIdx.z;
    const float* Wm = (z == 0) ? Wq : (z == 1) ? Wk : Wv;
    const float* bm = (z == 0) ? bq : (z == 1) ? bk : bv;

    __shared__ float Xs[64][17];
    __shared__ float Ws[16][65];

    int tx = threadIdx.x, ty = threadIdx.y;
    int tid = ty * 16 + tx;
    int rowBase = blockIdx.y * 64;
    int colBase = blockIdx.x * 64;

    float acc[4][4];
    #pragma unroll
    for (int i = 0; i < 4; i++)
        #pragma unroll
        for (int j = 0; j < 4; j++) acc[i][j] = 0.f;

    for (int kk = 0; kk < E; kk += 16) {
        #pragma unroll
        for (int i = tid; i < 64 * 16; i += 256) {
            int m = i >> 4, t = i & 15;
            Xs[m][t] = X[(size_t)(rowBase + m) * E + kk + t];
        }
        #pragma unroll
        for (int i = tid; i < 16 * 64; i += 256) {
            int t = i >> 6, n = i & 63;
            Ws[t][n] = Wm[(size_t)(kk + t) * E + colBase + n];
        }
        __syncthreads();
        #pragma unroll
        for (int t = 0; t < 16; t++) {
            float a[4], bb[4];
            #pragma unroll
            for (int i = 0; i < 4; i++) a[i] = Xs[ty * 4 + i][t];
            #pragma unroll
            for (int j = 0; j < 4; j++) bb[j] = Ws[t][tx * 4 + j];
            #pragma unroll
            for (int i = 0; i < 4; i++)
                #pragma unroll
                for (int j = 0; j < 4; j++)
                    acc[i][j] = fmaf(a[i], bb[j], acc[i][j]);
        }
        __syncthreads();
    }

    #pragma unroll
    for (int i = 0; i < 4; i++) {
        int mg = rowBase + ty * 4 + i;
        int b = mg / L, l = mg % L;
        #pragma unroll
        for (int j = 0; j < 4; j++) {
            int c = colBase + tx * 4 + j;
            float val = acc[i][j] + bm[c];
            int h = c >> 6;
            if (z < 2) {
                int d = (c >> 3) & 7, s = c & 7;
                float* dst = (z == 0) ? g_Q : g_K;
                dst[((((size_t)(b * H + h) * D + d) * L) + l) * DS + s] = val;
            } else {
                g_V[(((size_t)(b * H + h) * L) + l) * DH + (c & 63)] = val;
            }
        }
    }
}

// ---------------------------------------------------------------------------
// Kernel 2: depth-softmax statistics pass. One warp = one (b,h,d,q) row.
// Computes row S2 = sum p^2, rowmax = 1/Z, ent = logZ - sum p*(s - smax)
// (with EPS clipping handled per element).
// grid: (QT, D, BH), 256 threads (8 warps = 8 q rows).
// ---------------------------------------------------------------------------
__global__ __launch_bounds__(256)
void attn_stats(const float* __restrict__ mask)
{
    int bh = blockIdx.z;
    int d  = blockIdx.y;
    int qt = blockIdx.x;
    int warp = threadIdx.x >> 5;
    int lane = threadIdx.x & 31;
    int q = qt * 8 + warp;
    int b = bh / H;

    const float* Kd = g_K + ((size_t)(bh * D + d) * L) * DS;
    const float* Qp = g_Q + ((size_t)(bh * D + d) * L + q) * DS;
    const float* mrow = mask + b * L;

    float qv[8];
    #pragma unroll
    for (int s = 0; s < 8; s++) qv[s] = Qp[s];

    float sc[24];
    float smax = -1e30f;
    #pragma unroll
    for (int j = 0; j < 24; j++) {
        int k = j * 32 + lane;
        const float4* kp = (const float4*)(Kd + (size_t)k * 8);
        float4 k0 = kp[0], k1 = kp[1];
        float s = qv[0]*k0.x + qv[1]*k0.y + qv[2]*k0.z + qv[3]*k0.w
                + qv[4]*k1.x + qv[5]*k1.y + qv[6]*k1.z + qv[7]*k1.w;
        s = fmaf(s, RSQRT_DS, mrow[k]);
        sc[j] = s;
        smax = fmaxf(smax, s);
    }
    #pragma unroll
    for (int o = 16; o; o >>= 1)
        smax = fmaxf(smax, __shfl_xor_sync(0xffffffffu, smax, o));

    float Z = 0.f;
    #pragma unroll
    for (int j = 0; j < 24; j++) {
        sc[j] -= smax;
        Z += __expf(sc[j]);
    }
    #pragma unroll
    for (int o = 16; o; o >>= 1) Z += __shfl_xor_sync(0xffffffffu, Z, o);

    float invZ = 1.f / Z;
    float logZ = __logf(Z);

    float S2 = 0.f, ent = 0.f;
    #pragma unroll
    for (int j = 0; j < 24; j++) {
        float e = __expf(sc[j]);
        float p = e * invZ;
        S2 = fmaf(p, p, S2);
        float lp = sc[j] - logZ;              // log(p)
        float term = (p >= 1e-6f) ? (-p * lp) : EPS_TERM;
        ent += term;
    }
    #pragma unroll
    for (int o = 16; o; o >>= 1) {
        S2  += __shfl_xor_sync(0xffffffffu, S2, o);
        ent += __shfl_xor_sync(0xffffffffu, ent, o);
    }
    float rmax = invZ;  // max p = exp(0)/Z

    __shared__ float sS2[8], sMx[8], sEn[8];
    if (lane == 0) { sS2[warp] = S2; sMx[warp] = rmax; sEn[warp] = ent; }
    __syncthreads();
    if (threadIdx.x == 0) {
        float a = 0, m = 0, e = 0;
        #pragma unroll
        for (int w = 0; w < 8; w++) { a += sS2[w]; m += sMx[w]; e += sEn[w]; }
        size_t idx = ((size_t)(bh * D + d) * QT + qt) * 3;
        g_part[idx + 0] = a;
        g_part[idx + 1] = m;
        g_part[idx + 2] = e;
    }
}

// ---------------------------------------------------------------------------
// Kernel 3: reduce partials over (h, qtile) per (b,d). Double precision.
// grid: B*D blocks, 256 threads.
// ---------------------------------------------------------------------------
__global__ __launch_bounds__(256)
void reduce_stats()
{
    int bd = blockIdx.x;
    int b = bd / D, d = bd % D;
    int t = threadIdx.x;

    double s2 = 0, mx = 0, en = 0;
    for (int i = t; i < H * QT; i += 256) {
        int h = i / QT, qt = i % QT;
        size_t idx = ((size_t)((b * H + h) * D + d) * QT + qt) * 3;
        s2 += (double)g_part[idx + 0];
        mx += (double)g_part[idx + 1];
        en += (double)g_part[idx + 2];
    }
    __shared__ double sh0[256], sh1[256], sh2[256];
    sh0[t] = s2; sh1[t] = mx; sh2[t] = en;
    __syncthreads();
    for (int o = 128; o; o >>= 1) {
        if (t < o) { sh0[t] += sh0[t+o]; sh1[t] += sh1[t+o]; sh2[t] += sh2[t+o]; }
        __syncthreads();
    }
    if (t == 0) {
        double n = (double)H * (double)L;
        double S2m = sh0[0] / n;
        g_stats[(b * D + d) * 4 + 0] = (float)((S2m - 1.0 / (double)L) / (double)(L - 1));
        g_stats[(b * D + d) * 4 + 1] = (float)(sh1[0] / n);
        g_stats[(b * D + d) * 4 + 2] = (float)(sh2[0] / n);
        g_stats[(b * D + d) * 4 + 3] = (float)S2m;
    }
}

// ---------------------------------------------------------------------------
// Kernel 4: min-max norm over D, score, softmax -> weights. Trivially small.
// ---------------------------------------------------------------------------
__global__ void compute_weights()
{
    int b = blockIdx.x;
    if (threadIdx.x != 0) return;

    float st[4][D], nrm[4][D];
    for (int d = 0; d < D; d++)
        for (int j = 0; j < 4; j++) st[j][d] = g_stats[(b * D + d) * 4 + j];

    for (int j = 0; j < 4; j++) {
        float mn = st[j][0], mx = st[j][0];
        for (int d = 1; d < D; d++) { mn = fminf(mn, st[j][d]); mx = fmaxf(mx, st[j][d]); }
        float den = fmaxf(mx - mn, 1e-12f);
        for (int d = 0; d < D; d++) nrm[j][d] = (st[j][d] - mn) / den;
    }
    // score = 0.5*var + 0.3*max + 0.2*hhi - 0.4*ent, scaled by ALPHA=2.5
    float sc[D], mxs = -1e30f;
    for (int d = 0; d < D; d++) {
        sc[d] = 2.5f * (0.5f * nrm[0][d] + 0.3f * nrm[1][d]
                        + 0.2f * nrm[3][d] - 0.4f * nrm[2][d]);
        mxs = fmaxf(mxs, sc[d]);
    }
    float Z = 0.f, e[D];
    for (int d = 0; d < D; d++) { e[d] = expf(sc[d] - mxs); Z += e[d]; }
    for (int d = 0; d < D; d++) g_w[b * D + d] = e[d] / Z;
}

// ---------------------------------------------------------------------------
// Kernel 5: recompute depth softmaxes, combine with weights -> attn4 (output).
// One warp = one (b,h,q) row over all D depths.
// grid: (QT, BH), 256 threads.
// ---------------------------------------------------------------------------
__global__ __launch_bounds__(256)
void attn_combine(const float* __restrict__ mask, float* __restrict__ out_attn)
{
    int bh = blockIdx.y;
    int qt = blockIdx.x;
    int warp = threadIdx.x >> 5;
    int lane = threadIdx.x & 31;
    int q = qt * 8 + warp;
    int b = bh / H;
    const float* mrow = mask + b * L;

    float acc[24];
    #pragma unroll
    for (int j = 0; j < 24; j++) acc[j] = 0.f;

    for (int d = 0; d < D; d++) {
        const float* Kd = g_K + ((size_t)(bh * D + d) * L) * DS;
        const float* Qp = g_Q + ((size_t)(bh * D + d) * L + q) * DS;
        float qv[8];
        #pragma unroll
        for (int s = 0; s < 8; s++) qv[s] = Qp[s];
        float wd = g_w[b * D + d];

        float sc[24];
        float smax = -1e30f;
        #pragma unroll
        for (int j = 0; j < 24; j++) {
            int k = j * 32 + lane;
            const float4* kp = (const float4*)(Kd + (size_t)k * 8);
            float4 k0 = kp[0], k1 = kp[1];
            float s = qv[0]*k0.x + qv[1]*k0.y + qv[2]*k0.z + qv[3]*k0.w
                    + qv[4]*k1.x + qv[5]*k1.y + qv[6]*k1.z + qv[7]*k1.w;
            s = fmaf(s, RSQRT_DS, mrow[k]);
            sc[j] = s;
            smax = fmaxf(smax, s);
        }
        #pragma unroll
        for (int o = 16; o; o >>= 1)
            smax = fmaxf(smax, __shfl_xor_sync(0xffffffffu, smax, o));

        float Z = 0.f;
        #pragma unroll
        for (int j = 0; j < 24; j++) {
            sc[j] = __expf(sc[j] - smax);
            Z += sc[j];
        }
        #pragma unroll
        for (int o = 16; o; o >>= 1) Z += __shfl_xor_sync(0xffffffffu, Z, o);

        float f = wd / Z;
        #pragma unroll
        for (int j = 0; j < 24; j++) acc[j] = fmaf(sc[j], f, acc[j]);
    }

    float* row = out_attn + ((size_t)bh * L + q) * L;
    #pragma unroll
    for (int j = 0; j < 24; j++) row[j * 32 + lane] = acc[j];
}

// ---------------------------------------------------------------------------
// Kernel 6: ctx = attn4 @ V  per (b,h). Tiled GEMM 768x768 @ 768x64.
// grid: (L/64, BH), 256 threads.
// ---------------------------------------------------------------------------
__global__ __launch_bounds__(256)
void ctx_gemm(const float* __restrict__ attn4, float* __restrict__ out)
{
    int bh = blockIdx.y;
    int b = bh / H, h = bh % H;
    int rowBase = blockIdx.x * 64;

    __shared__ float As[64][17];
    __shared__ float Vs[16][65];

    int tx = threadIdx.x, ty = threadIdx.y;
    int tid = ty * 16 + tx;

    const float* A  = attn4 + (size_t)bh * L * L;
    const float* Vp = g_V + (size_t)bh * L * DH;

    float acc[4][4];
    #pragma unroll
    for (int i = 0; i < 4; i++)
        #pragma unroll
        for (int j = 0; j < 4; j++) acc[i][j] = 0.f;

    for (int kk = 0; kk < L; kk += 16) {
        #pragma unroll
        for (int i = tid; i < 64 * 16; i += 256) {
            int m = i >> 4, t = i & 15;
            As[m][t] = A[(size_t)(rowBase + m) * L + kk + t];
        }
        #pragma unroll
        for (int i = tid; i < 16 * 64; i += 256) {
            int t = i >> 6, n = i & 63;
            Vs[t][n] = Vp[(size_t)(kk + t) * DH + n];
        }
        __syncthreads();
        #pragma unroll
        for (int t = 0; t < 16; t++) {
            float a[4], bb[4];
            #pragma unroll
            for (int i = 0; i < 4; i++) a[i] = As[ty * 4 + i][t];
            #pragma unroll
            for (int j = 0; j < 4; j++) bb[j] = Vs[t][tx * 4 + j];
            #pragma unroll
            for (int i = 0; i < 4; i++)
                #pragma unroll
                for (int j = 0; j < 4; j++)
                    acc[i][j] = fmaf(a[i], bb[j], acc[i][j]);
        }
        __syncthreads();
    }

    #pragma unroll
    for (int i = 0; i < 4; i++) {
        int l = rowBase + ty * 4 + i;
        #pragma unroll
        for (int j = 0; j < 4; j++) {
            int dh = tx * 4 + j;
            out[((size_t)(b * L + l)) * E + h * DH + dh] = acc[i][j];
        }
    }
}

// ---------------------------------------------------------------------------
extern "C" void kernel_launch(void* const* d_in, const int* in_sizes, int n_in,
                              void* d_out, int out_size)
{
    const float* X    = (const float*)d_in[0];
    const float* mask = (const float*)d_in[1];
    const float* Wq   = (const float*)d_in[2];
    const float* bq   = (const float*)d_in[3];
    const float* Wk   = (const float*)d_in[4];
    const float* bk   = (const float*)d_in[5];
    const float* Wv   = (const float*)d_in[6];
    const float* bv   = (const float*)d_in[7];

    float* out   = (float*)d_out;
    float* ctx   = out;                          // [B, L, E]
    float* attn4 = out + (size_t)B * L * E;      // [B, H, L, L]

    qkv_gemm<<<dim3(E / 64, (B * L) / 64, 3), dim3(16, 16)>>>(X, Wq, bq, Wk, bk, Wv, bv);
    attn_stats<<<dim3(QT, D, BH), 256>>>(mask);
    reduce_stats<<<B * D, 256>>>();
    compute_weights<<<B, 32>>>();
    attn_combine<<<dim3(QT, BH), 256>>>(mask, attn4);
    ctx_gemm<<<dim3(L / 64, BH), dim3(16, 16)>>>(attn4, ctx);
}

// round 3
// speedup vs baseline: 1.0037x; 1.0037x over previous
#include <cuda_runtime.h>
#include <math.h>

// Problem constants
#define B   2
#define L   768
#define H   12
#define DH  64
#define D   8
#define DS  8
#define E   768
#define BH  (B*H)
#define QT  96          // q-tiles: 8 rows per block -> 96 tiles of L=768
#define NPART (BH*D*QT)

#define RSQRT_DS 0.35355339059327373f   // 1/sqrt(8)
#define EPS_TERM 1.3815510557964274e-5f // -1e-6 * ln(1e-6)

// Scratch (static device arrays; no runtime allocation)
__device__ float g_Q[BH*D*L*DS];     // [b,h,d,l,s]
__device__ float g_K[BH*D*L*DS];     // [b,h,d,l,s]
__device__ float g_V[BH*L*DH];       // [b,h,l,dh]
__device__ float g_part[NPART*3];    // per-block partial sums (S2, rowmax, ent)
__device__ float g_stats[B*D*4];     // var, max, ent, hhi
__device__ float g_w[B*D];           // depth weights

// ---------------------------------------------------------------------------
// Kernel 1: QKV projections. z = 0:Q, 1:K, 2:V.
// C[1536,768] = X[1536,768] @ W[768,768] + b, stored into transposed layouts.
// ---------------------------------------------------------------------------
__global__ __launch_bounds__(256)
void qkv_gemm(const float* __restrict__ X,
              const float* __restrict__ Wq, const float* __restrict__ bq,
              const float* __restrict__ Wk, const float* __restrict__ bk,
              const float* __restrict__ Wv, const float* __restrict__ bv)
{
    int z = blockIdx.z;
    const float* Wm = (z == 0) ? Wq : (z == 1) ? Wk : Wv;
    const float* bm = (z == 0) ? bq : (z == 1) ? bk : bv;

    __shared__ float Xs[64][17];
    __shared__ float Ws[16][65];

    int tx = threadIdx.x, ty = threadIdx.y;
    int tid = ty * 16 + tx;
    int rowBase = blockIdx.y * 64;
    int colBase = blockIdx.x * 64;

    float acc[4][4];
    #pragma unroll
    for (int i = 0; i < 4; i++)
        #pragma unroll
        for (int j = 0; j < 4; j++) acc[i][j] = 0.f;

    for (int kk = 0; kk < E; kk += 16) {
        #pragma unroll
        for (int i = tid; i < 64 * 16; i += 256) {
            int m = i >> 4, t = i & 15;
            Xs[m][t] = X[(size_t)(rowBase + m) * E + kk + t];
        }
        #pragma unroll
        for (int i = tid; i < 16 * 64; i += 256) {
            int t = i >> 6, n = i & 63;
            Ws[t][n] = Wm[(size_t)(kk + t) * E + colBase + n];
        }
        __syncthreads();
        #pragma unroll
        for (int t = 0; t < 16; t++) {
            float a[4], bb[4];
            #pragma unroll
            for (int i = 0; i < 4; i++) a[i] = Xs[ty * 4 + i][t];
            #pragma unroll
            for (int j = 0; j < 4; j++) bb[j] = Ws[t][tx * 4 + j];
            #pragma unroll
            for (int i = 0; i < 4; i++)
                #pragma unroll
                for (int j = 0; j < 4; j++)
                    acc[i][j] = fmaf(a[i], bb[j], acc[i][j]);
        }
        __syncthreads();
    }

    #pragma unroll
    for (int i = 0; i < 4; i++) {
        int mg = rowBase + ty * 4 + i;
        int b = mg / L, l = mg % L;
        #pragma unroll
        for (int j = 0; j < 4; j++) {
            int c = colBase + tx * 4 + j;
            float val = acc[i][j] + bm[c];
            int h = c >> 6;
            if (z < 2) {
                int d = (c >> 3) & 7, s = c & 7;
                float* dst = (z == 0) ? g_Q : g_K;
                dst[((((size_t)(b * H + h) * D + d) * L) + l) * DS + s] = val;
            } else {
                g_V[(((size_t)(b * H + h) * L) + l) * DH + (c & 63)] = val;
            }
        }
    }
}

// ---------------------------------------------------------------------------
// Kernel 2: depth-softmax statistics pass. One warp = one (b,h,d,q) row.
// Computes row S2 = sum p^2, rowmax = 1/Z, ent = logZ - sum p*(s - smax)
// (with EPS clipping handled per element).
// grid: (QT, D, BH), 256 threads (8 warps = 8 q rows).
// ---------------------------------------------------------------------------
__global__ __launch_bounds__(256)
void attn_stats(const float* __restrict__ mask)
{
    int bh = blockIdx.z;
    int d  = blockIdx.y;
    int qt = blockIdx.x;
    int warp = threadIdx.x >> 5;
    int lane = threadIdx.x & 31;
    int q = qt * 8 + warp;
    int b = bh / H;

    const float* Kd = g_K + ((size_t)(bh * D + d) * L) * DS;
    const float* Qp = g_Q + ((size_t)(bh * D + d) * L + q) * DS;
    const float* mrow = mask + b * L;

    float qv[8];
    #pragma unroll
    for (int s = 0; s < 8; s++) qv[s] = Qp[s];

    float sc[24];
    float smax = -1e30f;
    #pragma unroll
    for (int j = 0; j < 24; j++) {
        int k = j * 32 + lane;
        const float4* kp = (const float4*)(Kd + (size_t)k * 8);
        float4 k0 = kp[0], k1 = kp[1];
        float s = qv[0]*k0.x + qv[1]*k0.y + qv[2]*k0.z + qv[3]*k0.w
                + qv[4]*k1.x + qv[5]*k1.y + qv[6]*k1.z + qv[7]*k1.w;
        s = fmaf(s, RSQRT_DS, mrow[k]);
        sc[j] = s;
        smax = fmaxf(smax, s);
    }
    #pragma unroll
    for (int o = 16; o; o >>= 1)
        smax = fmaxf(smax, __shfl_xor_sync(0xffffffffu, smax, o));

    float Z = 0.f;
    #pragma unroll
    for (int j = 0; j < 24; j++) {
        sc[j] -= smax;
        Z += __expf(sc[j]);
    }
    #pragma unroll
    for (int o = 16; o; o >>= 1) Z += __shfl_xor_sync(0xffffffffu, Z, o);

    float invZ = 1.f / Z;
    float logZ = __logf(Z);

    float S2 = 0.f, ent = 0.f;
    #pragma unroll
    for (int j = 0; j < 24; j++) {
        float e = __expf(sc[j]);
        float p = e * invZ;
        S2 = fmaf(p, p, S2);
        float lp = sc[j] - logZ;              // log(p)
        float term = (p >= 1e-6f) ? (-p * lp) : EPS_TERM;
        ent += term;
    }
    #pragma unroll
    for (int o = 16; o; o >>= 1) {
        S2  += __shfl_xor_sync(0xffffffffu, S2, o);
        ent += __shfl_xor_sync(0xffffffffu, ent, o);
    }
    float rmax = invZ;  // max p = exp(0)/Z

    __shared__ float sS2[8], sMx[8], sEn[8];
    if (lane == 0) { sS2[warp] = S2; sMx[warp] = rmax; sEn[warp] = ent; }
    __syncthreads();
    if (threadIdx.x == 0) {
        float a = 0, m = 0, e = 0;
        #pragma unroll
        for (int w = 0; w < 8; w++) { a += sS2[w]; m += sMx[w]; e += sEn[w]; }
        size_t idx = ((size_t)(bh * D + d) * QT + qt) * 3;
        g_part[idx + 0] = a;
        g_part[idx + 1] = m;
        g_part[idx + 2] = e;
    }
}

// ---------------------------------------------------------------------------
// Kernel 3: reduce partials over (h, qtile) per (b,d). Double precision.
// grid: B*D blocks, 256 threads.
// ---------------------------------------------------------------------------
__global__ __launch_bounds__(256)
void reduce_stats()
{
    int bd = blockIdx.x;
    int b = bd / D, d = bd % D;
    int t = threadIdx.x;

    double s2 = 0, mx = 0, en = 0;
    for (int i = t; i < H * QT; i += 256) {
        int h = i / QT, qt = i % QT;
        size_t idx = ((size_t)((b * H + h) * D + d) * QT + qt) * 3;
        s2 += (double)g_part[idx + 0];
        mx += (double)g_part[idx + 1];
        en += (double)g_part[idx + 2];
    }
    __shared__ double sh0[256], sh1[256], sh2[256];
    sh0[t] = s2; sh1[t] = mx; sh2[t] = en;
    __syncthreads();
    for (int o = 128; o; o >>= 1) {
        if (t < o) { sh0[t] += sh0[t+o]; sh1[t] += sh1[t+o]; sh2[t] += sh2[t+o]; }
        __syncthreads();
    }
    if (t == 0) {
        double n = (double)H * (double)L;
        double S2m = sh0[0] / n;
        g_stats[(b * D + d) * 4 + 0] = (float)((S2m - 1.0 / (double)L) / (double)(L - 1));
        g_stats[(b * D + d) * 4 + 1] = (float)(sh1[0] / n);
        g_stats[(b * D + d) * 4 + 2] = (float)(sh2[0] / n);
        g_stats[(b * D + d) * 4 + 3] = (float)S2m;
    }
}

// ---------------------------------------------------------------------------
// Kernel 4: min-max norm over D, score, softmax -> weights. Trivially small.
// ---------------------------------------------------------------------------
__global__ void compute_weights()
{
    int b = blockIdx.x;
    if (threadIdx.x != 0) return;

    float st[4][D], nrm[4][D];
    for (int d = 0; d < D; d++)
        for (int j = 0; j < 4; j++) st[j][d] = g_stats[(b * D + d) * 4 + j];

    for (int j = 0; j < 4; j++) {
        float mn = st[j][0], mx = st[j][0];
        for (int d = 1; d < D; d++) { mn = fminf(mn, st[j][d]); mx = fmaxf(mx, st[j][d]); }
        float den = fmaxf(mx - mn, 1e-12f);
        for (int d = 0; d < D; d++) nrm[j][d] = (st[j][d] - mn) / den;
    }
    // score = 0.5*var + 0.3*max + 0.2*hhi - 0.4*ent, scaled by ALPHA=2.5
    float sc[D], mxs = -1e30f;
    for (int d = 0; d < D; d++) {
        sc[d] = 2.5f * (0.5f * nrm[0][d] + 0.3f * nrm[1][d]
                        + 0.2f * nrm[3][d] - 0.4f * nrm[2][d]);
        mxs = fmaxf(mxs, sc[d]);
    }
    float Z = 0.f, e[D];
    for (int d = 0; d < D; d++) { e[d] = expf(sc[d] - mxs); Z += e[d]; }
    for (int d = 0; d < D; d++) g_w[b * D + d] = e[d] / Z;
}

// ---------------------------------------------------------------------------
// Kernel 5: recompute depth softmaxes, combine with weights -> attn4 (output).
// One warp = one (b,h,q) row over all D depths.
// grid: (QT, BH), 256 threads.
// ---------------------------------------------------------------------------
__global__ __launch_bounds__(256)
void attn_combine(const float* __restrict__ mask, float* __restrict__ out_attn)
{
    int bh = blockIdx.y;
    int qt = blockIdx.x;
    int warp = threadIdx.x >> 5;
    int lane = threadIdx.x & 31;
    int q = qt * 8 + warp;
    int b = bh / H;
    const float* mrow = mask + b * L;

    float acc[24];
    #pragma unroll
    for (int j = 0; j < 24; j++) acc[j] = 0.f;

    for (int d = 0; d < D; d++) {
        const float* Kd = g_K + ((size_t)(bh * D + d) * L) * DS;
        const float* Qp = g_Q + ((size_t)(bh * D + d) * L + q) * DS;
        float qv[8];
        #pragma unroll
        for (int s = 0; s < 8; s++) qv[s] = Qp[s];
        float wd = g_w[b * D + d];

        float sc[24];
        float smax = -1e30f;
        #pragma unroll
        for (int j = 0; j < 24; j++) {
            int k = j * 32 + lane;
            const float4* kp = (const float4*)(Kd + (size_t)k * 8);
            float4 k0 = kp[0], k1 = kp[1];
            float s = qv[0]*k0.x + qv[1]*k0.y + qv[2]*k0.z + qv[3]*k0.w
                    + qv[4]*k1.x + qv[5]*k1.y + qv[6]*k1.z + qv[7]*k1.w;
            s = fmaf(s, RSQRT_DS, mrow[k]);
            sc[j] = s;
            smax = fmaxf(smax, s);
        }
        #pragma unroll
        for (int o = 16; o; o >>= 1)
            smax = fmaxf(smax, __shfl_xor_sync(0xffffffffu, smax, o));

        float Z = 0.f;
        #pragma unroll
        for (int j = 0; j < 24; j++) {
            sc[j] = __expf(sc[j] - smax);
            Z += sc[j];
        }
        #pragma unroll
        for (int o = 16; o; o >>= 1) Z += __shfl_xor_sync(0xffffffffu, Z, o);

        float f = wd / Z;
        #pragma unroll
        for (int j = 0; j < 24; j++) acc[j] = fmaf(sc[j], f, acc[j]);
    }

    float* row = out_attn + ((size_t)bh * L + q) * L;
    #pragma unroll
    for (int j = 0; j < 24; j++) row[j * 32 + lane] = acc[j];
}

// ---------------------------------------------------------------------------
// Kernel 6: ctx = attn4 @ V  per (b,h). Tiled GEMM 768x768 @ 768x64.
// grid: (L/64, BH), 256 threads.
// ---------------------------------------------------------------------------
__global__ __launch_bounds__(256)
void ctx_gemm(const float* __restrict__ attn4, float* __restrict__ out)
{
    int bh = blockIdx.y;
    int b = bh / H, h = bh % H;
    int rowBase = blockIdx.x * 64;

    __shared__ float As[64][17];
    __shared__ float Vs[16][65];

    int tx = threadIdx.x, ty = threadIdx.y;
    int tid = ty * 16 + tx;

    const float* A  = attn4 + (size_t)bh * L * L;
    const float* Vp = g_V + (size_t)bh * L * DH;

    float acc[4][4];
    #pragma unroll
    for (int i = 0; i < 4; i++)
        #pragma unroll
        for (int j = 0; j < 4; j++) acc[i][j] = 0.f;

    for (int kk = 0; kk < L; kk += 16) {
        #pragma unroll
        for (int i = tid; i < 64 * 16; i += 256) {
            int m = i >> 4, t = i & 15;
            As[m][t] = A[(size_t)(rowBase + m) * L + kk + t];
        }
        #pragma unroll
        for (int i = tid; i < 16 * 64; i += 256) {
            int t = i >> 6, n = i & 63;
            Vs[t][n] = Vp[(size_t)(kk + t) * DH + n];
        }
        __syncthreads();
        #pragma unroll
        for (int t = 0; t < 16; t++) {
            float a[4], bb[4];
            #pragma unroll
            for (int i = 0; i < 4; i++) a[i] = As[ty * 4 + i][t];
            #pragma unroll
            for (int j = 0; j < 4; j++) bb[j] = Vs[t][tx * 4 + j];
            #pragma unroll
            for (int i = 0; i < 4; i++)
                #pragma unroll
                for (int j = 0; j < 4; j++)
                    acc[i][j] = fmaf(a[i], bb[j], acc[i][j]);
        }
        __syncthreads();
    }

    #pragma unroll
    for (int i = 0; i < 4; i++) {
        int l = rowBase + ty * 4 + i;
        #pragma unroll
        for (int j = 0; j < 4; j++) {
            int dh = tx * 4 + j;
            out[((size_t)(b * L + l)) * E + h * DH + dh] = acc[i][j];
        }
    }
}

// ---------------------------------------------------------------------------
extern "C" void kernel_launch(void* const* d_in, const int* in_sizes, int n_in,
                              void* d_out, int out_size)
{
    const float* X    = (const float*)d_in[0];
    const float* mask = (const float*)d_in[1];
    const float* Wq   = (const float*)d_in[2];
    const float* bq   = (const float*)d_in[3];
    const float* Wk   = (const float*)d_in[4];
    const float* bk   = (const float*)d_in[5];
    const float* Wv   = (const float*)d_in[6];
    const float* bv   = (const float*)d_in[7];

    float* out   = (float*)d_out;
    float* ctx   = out;                          // [B, L, E]
    float* attn4 = out + (size_t)B * L * E;      // [B, H, L, L]

    qkv_gemm<<<dim3(E / 64, (B * L) / 64, 3), dim3(16, 16)>>>(X, Wq, bq, Wk, bk, Wv, bv);
    attn_stats<<<dim3(QT, D, BH), 256>>>(mask);
    reduce_stats<<<B * D, 256>>>();
    compute_weights<<<B, 32>>>();
    attn_combine<<<dim3(QT, BH), 256>>>(mask, attn4);
    ctx_gemm<<<dim3(L / 64, BH), dim3(16, 16)>>>(attn4, ctx);
}

// round 5
// speedup vs baseline: 1.6298x; 1.6238x over previous
#include <cuda_runtime.h>
#include <math.h>

typedef unsigned long long ull;

// Problem constants
#define B   2
#define L   768
#define H   12
#define DH  64
#define D   8
#define DS  8
#define E   768
#define BH  (B*H)

#define SQT 24            // stats q-tiles: 32 rows per block
#define CQT 96            // combine q-tiles: 8 rows per block
#define NPART (BH*D*SQT)

#define RSQRT_DS 0.35355339059327373f   // 1/sqrt(8)

// Scratch (static device arrays; no runtime allocation)
__device__ float g_Q[BH*D*L*DS];     // [b,h,d,l,s]
__device__ float g_K[BH*D*L*DS];     // [b,h,d,l,s]
__device__ float g_V[BH*L*DH];       // [b,h,l,dh]
__device__ float g_invZ[BH*D*L];     // per-row 1/Z
__device__ float g_part[NPART*3];    // per-block partial sums (hhi, max, ent)
__device__ float g_stats[B*D*4];     // var, max, ent, hhi
__device__ float g_w[B*D];           // depth weights

// ---------------------------------------------------------------------------
// f32x2 packed helpers
// ---------------------------------------------------------------------------
__device__ __forceinline__ ull ffma2(ull a, ull b, ull c) {
    ull d_; asm("fma.rn.f32x2 %0, %1, %2, %3;" : "=l"(d_) : "l"(a), "l"(b), "l"(c));
    return d_;
}
__device__ __forceinline__ ull fmul2(ull a, ull b) {
    ull d_; asm("mul.rn.f32x2 %0, %1, %2;" : "=l"(d_) : "l"(a), "l"(b));
    return d_;
}
__device__ __forceinline__ float2 unpk(ull v) {
    float2 f; asm("mov.b64 {%0, %1}, %2;" : "=f"(f.x), "=f"(f.y) : "l"(v));
    return f;
}

// ---------------------------------------------------------------------------
// Kernel 1: QKV projections with f32x2.  Tile 128(M) x 64(N), K-step 16.
// 256 threads (16x16), micro-tile 8 rows (4 row-pairs) x 4 cols per thread.
// grid: (E/64, (B*L)/128, 3)
// ---------------------------------------------------------------------------
__global__ __launch_bounds__(256)
void qkv_gemm(const float* __restrict__ X,
              const float* __restrict__ Wq, const float* __restrict__ bq,
              const float* __restrict__ Wk, const float* __restrict__ bk,
              const float* __restrict__ Wv, const float* __restrict__ bv)
{
    int z = blockIdx.z;
    const float* Wm = (z == 0) ? Wq : (z == 1) ? Wk : Wv;
    const float* bm = (z == 0) ? bq : (z == 1) ? bk : bv;

    __shared__ float  As[16][132];     // k-major, m contiguous
    __shared__ float2 Ws2[16][66];     // duplicated B operand

    int tx = threadIdx.x & 15;
    int ty = threadIdx.x >> 4;
    int tid = threadIdx.x;
    int rowBase = blockIdx.y * 128;
    int colBase = blockIdx.x * 64;

    ull acc[4][4];
    #pragma unroll
    for (int i = 0; i < 4; i++)
        #pragma unroll
        for (int j = 0; j < 4; j++) acc[i][j] = 0ull;

    for (int kk = 0; kk < E; kk += 16) {
        __syncthreads();
        {
            int r = tid >> 1, kc = (tid & 1) * 8;
            const float* xp = X + (size_t)(rowBase + r) * E + kk + kc;
            float4 x0 = *(const float4*)xp;
            float4 x1 = *(const float4*)(xp + 4);
            As[kc + 0][r] = x0.x; As[kc + 1][r] = x0.y;
            As[kc + 2][r] = x0.z; As[kc + 3][r] = x0.w;
            As[kc + 4][r] = x1.x; As[kc + 5][r] = x1.y;
            As[kc + 6][r] = x1.z; As[kc + 7][r] = x1.w;

            int t = tid >> 4, n = (tid & 15) * 4;
            const float* wp = Wm + (size_t)(kk + t) * E + colBase + n;
            float4 wv = *(const float4*)wp;
            Ws2[t][n + 0] = make_float2(wv.x, wv.x);
            Ws2[t][n + 1] = make_float2(wv.y, wv.y);
            Ws2[t][n + 2] = make_float2(wv.z, wv.z);
            Ws2[t][n + 3] = make_float2(wv.w, wv.w);
        }
        __syncthreads();
        #pragma unroll
        for (int t = 0; t < 16; t++) {
            ulonglong2 a0 = *(const ulonglong2*)&As[t][ty * 8];
            ulonglong2 a1 = *(const ulonglong2*)&As[t][ty * 8 + 4];
            ulonglong2 b0 = *(const ulonglong2*)&Ws2[t][tx * 4];
            ulonglong2 b1 = *(const ulonglong2*)&Ws2[t][tx * 4 + 2];
            ull ap[4] = {a0.x, a0.y, a1.x, a1.y};
            ull bd[4] = {b0.x, b0.y, b1.x, b1.y};
            #pragma unroll
            for (int ip = 0; ip < 4; ip++)
                #pragma unroll
                for (int j = 0; j < 4; j++)
                    acc[ip][j] = ffma2(ap[ip], bd[j], acc[ip][j]);
        }
    }

    float bias[4];
    #pragma unroll
    for (int j = 0; j < 4; j++) bias[j] = bm[colBase + tx * 4 + j];

    int c0 = colBase + tx * 4;
    int h = c0 >> 6;
    int dd = (c0 >> 3) & 7;
    int s0 = c0 & 7;

    #pragma unroll
    for (int ip = 0; ip < 4; ip++) {
        int l0g = rowBase + ty * 8 + ip * 2;
        float2 p0 = unpk(acc[ip][0]), p1 = unpk(acc[ip][1]);
        float2 p2 = unpk(acc[ip][2]), p3 = unpk(acc[ip][3]);
        float4 r0 = make_float4(p0.x + bias[0], p1.x + bias[1], p2.x + bias[2], p3.x + bias[3]);
        float4 r1 = make_float4(p0.y + bias[0], p1.y + bias[1], p2.y + bias[2], p3.y + bias[3]);
        #pragma unroll
        for (int rr = 0; rr < 2; rr++) {
            int lg = l0g + rr;
            int bb = lg / L, l = lg - bb * L;
            float4 v = rr ? r1 : r0;
            if (z < 2) {
                float* dst = (z == 0 ? g_Q : g_K)
                    + (((size_t)(bb * H + h) * D + dd) * L + l) * 8 + s0;
                *(float4*)dst = v;
            } else {
                float* dst = g_V + ((size_t)(bb * H + h) * L + l) * 64 + (tx * 4);
                *(float4*)dst = v;
            }
        }
    }
}

// ---------------------------------------------------------------------------
// Kernel 2: statistics pass (single loop, no-rescale softmax, one exp).
// Each warp: 4 q rows x full K, lane strided over k.  Block = 32 rows.
// grid: (SQT, D, BH), 256 threads.
// ---------------------------------------------------------------------------
__global__ __launch_bounds__(256)
void attn_stats(const float* __restrict__ mask)
{
    int bh = blockIdx.z, d = blockIdx.y, qt = blockIdx.x;
    int w = threadIdx.x >> 5, lane = threadIdx.x & 31;
    int b = bh / H;
    int q0 = qt * 32 + w * 4;

    const float* Kd = g_K + ((size_t)(bh * D + d) * L) * DS;
    const float* Qd = g_Q + ((size_t)(bh * D + d) * L) * DS;
    const float* mrow = mask + b * L;

    ull qp[4][4];
    #pragma unroll
    for (int r = 0; r < 4; r++) {
        const ulonglong2* qq = (const ulonglong2*)(Qd + (size_t)(q0 + r) * 8);
        ulonglong2 a = qq[0], bb2 = qq[1];
        qp[r][0] = a.x; qp[r][1] = a.y; qp[r][2] = bb2.x; qp[r][3] = bb2.y;
    }

    float Z[4] = {0, 0, 0, 0}, S2[4] = {0, 0, 0, 0};
    float ES[4] = {0, 0, 0, 0}, EM[4] = {0, 0, 0, 0};

    #pragma unroll 6
    for (int j = 0; j < 24; j++) {
        int k = j * 32 + lane;
        const ulonglong2* kp = (const ulonglong2*)(Kd + (size_t)k * 8);
        ulonglong2 kv0 = kp[0], kv1 = kp[1];
        float mk = __ldg(mrow + k);
        #pragma unroll
        for (int r = 0; r < 4; r++) {
            ull t = ffma2(qp[r][0], kv0.x,
                    ffma2(qp[r][1], kv0.y,
                    ffma2(qp[r][2], kv1.x,
                    fmul2(qp[r][3], kv1.y))));
            float2 u = unpk(t);
            float s = fmaf(u.x + u.y, RSQRT_DS, mk);
            float e = __expf(s);
            Z[r] += e;
            S2[r] = fmaf(e, e, S2[r]);
            ES[r] = fmaf(e, s, ES[r]);
            EM[r] = fmaxf(EM[r], e);
        }
    }

    #pragma unroll
    for (int r = 0; r < 4; r++) {
        #pragma unroll
        for (int o = 16; o; o >>= 1) {
            Z[r]  += __shfl_xor_sync(0xffffffffu, Z[r],  o);
            S2[r] += __shfl_xor_sync(0xffffffffu, S2[r], o);
            ES[r] += __shfl_xor_sync(0xffffffffu, ES[r], o);
            EM[r]  = fmaxf(EM[r], __shfl_xor_sync(0xffffffffu, EM[r], o));
        }
    }

    __shared__ float sH[8], sM[8], sE[8];
    if (lane == 0) {
        float hh = 0, mm = 0, ee = 0;
        #pragma unroll
        for (int r = 0; r < 4; r++) {
            float invZ = 1.f / Z[r];
            g_invZ[((size_t)(bh * D + d)) * L + q0 + r] = invZ;
            hh += S2[r] * invZ * invZ;
            mm += EM[r] * invZ;
            ee += __logf(Z[r]) - ES[r] * invZ;
        }
        sH[w] = hh; sM[w] = mm; sE[w] = ee;
    }
    __syncthreads();
    if (threadIdx.x == 0) {
        float hh = 0, mm = 0, ee = 0;
        #pragma unroll
        for (int ww = 0; ww < 8; ww++) { hh += sH[ww]; mm += sM[ww]; ee += sE[ww]; }
        size_t idx = ((size_t)(bh * D + d) * SQT + qt) * 3;
        g_part[idx + 0] = hh;  // sum of row hhi (= sum p^2)
        g_part[idx + 1] = mm;  // sum of row max
        g_part[idx + 2] = ee;  // sum of row entropy
    }
}

// ---------------------------------------------------------------------------
// Kernel 3: reduce partials over (h, qtile) per (b,d). Double precision.
// grid: B*D blocks, 256 threads.
// ---------------------------------------------------------------------------
__global__ __launch_bounds__(256)
void reduce_stats()
{
    int bd = blockIdx.x;
    int b = bd / D, d = bd % D;
    int t = threadIdx.x;

    double s2 = 0, mx = 0, en = 0;
    for (int i = t; i < H * SQT; i += 256) {
        int h = i / SQT, qt = i % SQT;
        size_t idx = ((size_t)((b * H + h) * D + d) * SQT + qt) * 3;
        s2 += (double)g_part[idx + 0];
        mx += (double)g_part[idx + 1];
        en += (double)g_part[idx + 2];
    }
    __shared__ double sh0[256], sh1[256], sh2[256];
    sh0[t] = s2; sh1[t] = mx; sh2[t] = en;
    __syncthreads();
    for (int o = 128; o; o >>= 1) {
        if (t < o) { sh0[t] += sh0[t+o]; sh1[t] += sh1[t+o]; sh2[t] += sh2[t+o]; }
        __syncthreads();
    }
    if (t == 0) {
        double n = (double)H * (double)L;
        double S2m = sh0[0] / n;
        g_stats[(b * D + d) * 4 + 0] = (float)((S2m - 1.0 / (double)L) / (double)(L - 1));
        g_stats[(b * D + d) * 4 + 1] = (float)(sh1[0] / n);
        g_stats[(b * D + d) * 4 + 2] = (float)(sh2[0] / n);
        g_stats[(b * D + d) * 4 + 3] = (float)S2m;
    }
}

// ---------------------------------------------------------------------------
// Kernel 4: min-max norm over D, score, softmax -> weights. Tiny.
// ---------------------------------------------------------------------------
__global__ void compute_weights()
{
    int b = blockIdx.x;
    if (threadIdx.x != 0) return;

    float st[4][D], nrm[4][D];
    for (int d = 0; d < D; d++)
        for (int j = 0; j < 4; j++) st[j][d] = g_stats[(b * D + d) * 4 + j];

    for (int j = 0; j < 4; j++) {
        float mn = st[j][0], mx = st[j][0];
        for (int d = 1; d < D; d++) { mn = fminf(mn, st[j][d]); mx = fmaxf(mx, st[j][d]); }
        float den = fmaxf(mx - mn, 1e-12f);
        for (int d = 0; d < D; d++) nrm[j][d] = (st[j][d] - mn) / den;
    }
    float sc[D], mxs = -1e30f;
    for (int d = 0; d < D; d++) {
        sc[d] = 2.5f * (0.5f * nrm[0][d] + 0.3f * nrm[1][d]
                        + 0.2f * nrm[3][d] - 0.4f * nrm[2][d]);
        mxs = fmaxf(mxs, sc[d]);
    }
    float Z = 0.f, e[D];
    for (int d = 0; d < D; d++) { e[d] = expf(sc[d] - mxs); Z += e[d]; }
    for (int d = 0; d < D; d++) g_w[b * D + d] = e[d] / Z;
}

// ---------------------------------------------------------------------------
// Kernel 5: combine pass -> attn4.  No reductions: uses stored invZ.
// Block = 8 q rows of one bh; warp w owns k in [w*96, w*96+96).
// Per element: dot -> exp -> fma.  grid: (CQT, BH), 256 threads.
// ---------------------------------------------------------------------------
__global__ __launch_bounds__(256)
void attn_combine(const float* __restrict__ mask, float* __restrict__ out_attn)
{
    int bh = blockIdx.y;
    int w = threadIdx.x >> 5, lane = threadIdx.x & 31;
    int b = bh / H;
    int q0 = blockIdx.x * 8;
    int kb = w * 96;
    const float* mrow = mask + b * L;

    __shared__ float sf[8][8];   // [r][d] = w_d * invZ(row r, depth d)
    if (threadIdx.x < 64) {
        int r = threadIdx.x >> 3, d = threadIdx.x & 7;
        sf[r][d] = g_w[b * D + d] *
                   g_invZ[((size_t)(bh * D + d)) * L + q0 + r];
    }
    __syncthreads();

    float mk[3];
    #pragma unroll
    for (int j = 0; j < 3; j++) mk[j] = __ldg(mrow + kb + j * 32 + lane);

    float acc[8][3];
    #pragma unroll
    for (int r = 0; r < 8; r++)
        #pragma unroll
        for (int j = 0; j < 3; j++) acc[r][j] = 0.f;

    for (int d = 0; d < D; d++) {
        const float* Kd = g_K + ((size_t)(bh * D + d) * L) * DS;
        const float* Qd = g_Q + ((size_t)(bh * D + d) * L) * DS;
        ull qp[8][4];
        #pragma unroll
        for (int r = 0; r < 8; r++) {
            const ulonglong2* qq = (const ulonglong2*)(Qd + (size_t)(q0 + r) * 8);
            ulonglong2 a = qq[0], bb2 = qq[1];
            qp[r][0] = a.x; qp[r][1] = a.y; qp[r][2] = bb2.x; qp[r][3] = bb2.y;
        }
        float fr[8];
        #pragma unroll
        for (int r = 0; r < 8; r++) fr[r] = sf[r][d];

        #pragma unroll
        for (int j = 0; j < 3; j++) {
            int k = kb + j * 32 + lane;
            const ulonglong2* kp = (const ulonglong2*)(Kd + (size_t)k * 8);
            ulonglong2 kv0 = kp[0], kv1 = kp[1];
            #pragma unroll
            for (int r = 0; r < 8; r++) {
                ull t = ffma2(qp[r][0], kv0.x,
                        ffma2(qp[r][1], kv0.y,
                        ffma2(qp[r][2], kv1.x,
                        fmul2(qp[r][3], kv1.y))));
                float2 u = unpk(t);
                float s = fmaf(u.x + u.y, RSQRT_DS, mk[j]);
                float e = __expf(s);
                acc[r][j] = fmaf(e, fr[r], acc[r][j]);
            }
        }
    }

    #pragma unroll
    for (int r = 0; r < 8; r++) {
        float* row = out_attn + ((size_t)bh * L + q0 + r) * L;
        #pragma unroll
        for (int j = 0; j < 3; j++) row[kb + j * 32 + lane] = acc[r][j];
    }
}

// ---------------------------------------------------------------------------
// Kernel 6: ctx = attn4 @ V per (b,h), f32x2.  Tile 128(M) x 64(N=DH).
// grid: (L/128, BH), 256 threads, micro 8x4.
// ---------------------------------------------------------------------------
__global__ __launch_bounds__(256)
void ctx_gemm(const float* __restrict__ attn4, float* __restrict__ out)
{
    int bh = blockIdx.y;
    int b = bh / H, h = bh % H;
    int rowBase = blockIdx.x * 128;

    __shared__ float  As[16][132];
    __shared__ float2 Vs2[16][66];

    int tx = threadIdx.x & 15;
    int ty = threadIdx.x >> 4;
    int tid = threadIdx.x;

    const float* A  = attn4 + (size_t)bh * L * L;
    const float* Vp = g_V + (size_t)bh * L * DH;

    ull acc[4][4];
    #pragma unroll
    for (int i = 0; i < 4; i++)
        #pragma unroll
        for (int j = 0; j < 4; j++) acc[i][j] = 0ull;

    for (int kk = 0; kk < L; kk += 16) {
        __syncthreads();
        {
            int r = tid >> 1, kc = (tid & 1) * 8;
            const float* ap = A + (size_t)(rowBase + r) * L + kk + kc;
            float4 a0 = *(const float4*)ap;
            float4 a1 = *(const float4*)(ap + 4);
            As[kc + 0][r] = a0.x; As[kc + 1][r] = a0.y;
            As[kc + 2][r] = a0.z; As[kc + 3][r] = a0.w;
            As[kc + 4][r] = a1.x; As[kc + 5][r] = a1.y;
            As[kc + 6][r] = a1.z; As[kc + 7][r] = a1.w;

            int t = tid >> 4, n = (tid & 15) * 4;
            const float* vp = Vp + (size_t)(kk + t) * DH + n;
            float4 vv = *(const float4*)vp;
            Vs2[t][n + 0] = make_float2(vv.x, vv.x);
            Vs2[t][n + 1] = make_float2(vv.y, vv.y);
            Vs2[t][n + 2] = make_float2(vv.z, vv.z);
            Vs2[t][n + 3] = make_float2(vv.w, vv.w);
        }
        __syncthreads();
        #pragma unroll
        for (int t = 0; t < 16; t++) {
            ulonglong2 a0 = *(const ulonglong2*)&As[t][ty * 8];
            ulonglong2 a1 = *(const ulonglong2*)&As[t][ty * 8 + 4];
            ulonglong2 b0 = *(const ulonglong2*)&Vs2[t][tx * 4];
            ulonglong2 b1 = *(const ulonglong2*)&Vs2[t][tx * 4 + 2];
            ull ap2[4] = {a0.x, a0.y, a1.x, a1.y};
            ull bd[4]  = {b0.x, b0.y, b1.x, b1.y};
            #pragma unroll
            for (int ip = 0; ip < 4; ip++)
                #pragma unroll
                for (int j = 0; j < 4; j++)
                    acc[ip][j] = ffma2(ap2[ip], bd[j], acc[ip][j]);
        }
    }

    #pragma unroll
    for (int ip = 0; ip < 4; ip++) {
        int l0 = rowBase + ty * 8 + ip * 2;
        float2 p0 = unpk(acc[ip][0]), p1 = unpk(acc[ip][1]);
        float2 p2 = unpk(acc[ip][2]), p3 = unpk(acc[ip][3]);
        float4 r0 = make_float4(p0.x, p1.x, p2.x, p3.x);
        float4 r1 = make_float4(p0.y, p1.y, p2.y, p3.y);
        float* d0 = out + ((size_t)(b * L + l0)) * E + h * DH + tx * 4;
        float* d1 = out + ((size_t)(b * L + l0 + 1)) * E + h * DH + tx * 4;
        *(float4*)d0 = r0;
        *(float4*)d1 = r1;
    }
}

// ---------------------------------------------------------------------------
extern "C" void kernel_launch(void* const* d_in, const int* in_sizes, int n_in,
                              void* d_out, int out_size)
{
    const float* X    = (const float*)d_in[0];
    const float* mask = (const float*)d_in[1];
    const float* Wq   = (const float*)d_in[2];
    const float* bq   = (const float*)d_in[3];
    const float* Wk   = (const float*)d_in[4];
    const float* bk   = (const float*)d_in[5];
    const float* Wv   = (const float*)d_in[6];
    const float* bv   = (const float*)d_in[7];

    float* out   = (float*)d_out;
    float* ctx   = out;                          // [B, L, E]
    float* attn4 = out + (size_t)B * L * E;      // [B, H, L, L]

    qkv_gemm<<<dim3(E / 64, (B * L) / 128, 3), 256>>>(X, Wq, bq, Wk, bk, Wv, bv);
    attn_stats<<<dim3(SQT, D, BH), 256>>>(mask);
    reduce_stats<<<B * D, 256>>>();
    compute_weights<<<B, 32>>>();
    attn_combine<<<dim3(CQT, BH), 256>>>(mask, attn4);
    ctx_gemm<<<dim3(L / 128, BH), 256>>>(attn4, ctx);
}